// round 9
// baseline (speedup 1.0000x reference)
#include <cuda_runtime.h>
#include <cuda_fp16.h>
#include <math.h>

#define ROWS 6144            // B*Np = 32*192

__device__ __half d_Ft0[32*250*64];     // stage0: x2 (10x25)
__device__ __half d_Ft1[32*1000*64];    // stage1: x1 (20x50)
__device__ __half d_Ft2[32*4000*64];    // stage2: x0 (40x100)
__device__ float d_prior[ROWS*72];
__device__ float d_g[3][ROWS*64];

__device__ __forceinline__ float sigm(float x) { return 1.0f / (1.0f + expf(-x)); }

__device__ __forceinline__ __half2 u2h(unsigned u) {
    return *reinterpret_cast<__half2*>(&u);
}
__device__ __forceinline__ unsigned h2u(__half2 h) {
    return *reinterpret_cast<unsigned*>(&h);
}

// ===========================================================================
// kT body: transpose+matmul, fp32 compute, fp16 store. 64px x 64cc, 256 thr.
// ===========================================================================
struct SmemT {
    float sin_[64][65];
    float sW[64*64];
};

__device__ __forceinline__ void kT_body(
    SmemT* sm, const float* __restrict__ feat, const float* __restrict__ Wg,
    __half* __restrict__ outp, int p0, int HW)
{
    int tid = threadIdx.x;
    for (int i = tid; i < 4096; i += 256) sm->sW[i] = Wg[i];
    for (int e = tid; e < 4096; e += 256) {
        int c = e >> 6, p = e & 63;
        int gp = p0 + p;
        int b = gp / HW, hw = gp - b * HW;
        sm->sin_[p][c] = feat[(size_t)(b * 64 + c) * HW + hw];
    }
    __syncthreads();

    int cgrp = tid & 15, pgrp = tid >> 4;
    float acc[4][4];
#pragma unroll
    for (int i = 0; i < 4; i++)
#pragma unroll
        for (int j = 0; j < 4; j++) acc[i][j] = 0.f;

#pragma unroll 8
    for (int c = 0; c < 64; c++) {
        float4 w4 = *(const float4*)&sm->sW[c * 64 + cgrp * 4];
#pragma unroll
        for (int pp = 0; pp < 4; pp++) {
            float sv = sm->sin_[pgrp * 4 + pp][c];
            acc[pp][0] = fmaf(sv, w4.x, acc[pp][0]);
            acc[pp][1] = fmaf(sv, w4.y, acc[pp][1]);
            acc[pp][2] = fmaf(sv, w4.z, acc[pp][2]);
            acc[pp][3] = fmaf(sv, w4.w, acc[pp][3]);
        }
    }
#pragma unroll
    for (int pp = 0; pp < 4; pp++) {
        __half2 h0 = __floats2half2_rn(acc[pp][0], acc[pp][1]);
        __half2 h1 = __floats2half2_rn(acc[pp][2], acc[pp][3]);
        uint2 q;
        q.x = h2u(h0);
        q.y = h2u(h1);
        *(uint2*)&outp[(size_t)(p0 + pgrp * 4 + pp) * 64 + cgrp * 4] = q;
    }
}

// ===========================================================================
// kS body: half2 sampling + gate-folded weights + relu + pair-max + mean.
// 2 rows per 256-thread block.
// ===========================================================================
struct SmemS {
    int      sidx[2][72][4];     // byte offsets of 4 corners
    __half2  sw2[2][72][4];      // bilinear weights * gate, broadcast
    float    sacc[2][4][64];
};

__device__ __forceinline__ void kS_body(
    SmemS* sm, int stage, int row0, int H, int W,
    const float* __restrict__ prior0, const float* __restrict__ l_weight)
{
    int tid = threadIdx.x;
    int htid = tid & 127, half = tid >> 7;
    int row = row0 + half;
    int b = row / 192, n = row - b * 192;

    if (htid < 72) {
        int o = htid;
        float px = (stage == 0) ? prior0[n * 72 + o] : d_prior[row * 72 + o];
        float gx = px * 2.0f - 1.0f;
        float ix = (gx + 1.0f) * 0.5f * (float)(W - 1);
        float yo = 1.0f - (float)o * (1.0f / 71.0f);
        float gy = yo * 2.0f - 1.0f;
        float iy = (gy + 1.0f) * 0.5f * (float)(H - 1);
        float ix0f = floorf(ix), iy0f = floorf(iy);
        float wx = ix - ix0f, wy = iy - iy0f;
        int ix0 = min(max((int)ix0f, 0), W - 1);
        int iy0 = min(max((int)iy0f, 0), H - 1);
        int ix1 = min(ix0 + 1, W - 1);
        int iy1 = min(iy0 + 1, H - 1);
        sm->sidx[half][o][0] = (iy0 * W + ix0) * 128;   // bytes (64 ch * 2B)
        sm->sidx[half][o][1] = (iy0 * W + ix1) * 128;
        sm->sidx[half][o][2] = (iy1 * W + ix0) * 128;
        sm->sidx[half][o][3] = (iy1 * W + ix1) * 128;
        float g = sigm(l_weight[o]);
        sm->sw2[half][o][0] = __float2half2_rn(g * (1.f - wx) * (1.f - wy));
        sm->sw2[half][o][1] = __float2half2_rn(g * wx * (1.f - wy));
        sm->sw2[half][o][2] = __float2half2_rn(g * (1.f - wx) * wy);
        sm->sw2[half][o][3] = __float2half2_rn(g * wx * wy);
    }
    __syncthreads();

    const __half* Ft = (stage == 0) ? d_Ft0 : (stage == 1 ? d_Ft1 : d_Ft2);
    const char* pbase = (const char*)(Ft + (size_t)b * ((size_t)H * W * 64))
                        + (htid & 15) * 8;             // + c4*4 halves
    int c4 = htid & 15, osub = htid >> 4;
    const __half2 z2 = __float2half2_rn(0.f);

    float4 acc = make_float4(0.f, 0.f, 0.f, 0.f);
#pragma unroll
    for (int it = 0; it < 9; it++) {
        int o = it * 8 + osub;
        const int* si = sm->sidx[half][o];
        uint2 q0 = *(const uint2*)(pbase + si[0]);
        uint2 q1 = *(const uint2*)(pbase + si[1]);
        uint2 q2 = *(const uint2*)(pbase + si[2]);
        uint2 q3 = *(const uint2*)(pbase + si[3]);
        __half2 w0 = sm->sw2[half][o][0], w1 = sm->sw2[half][o][1];
        __half2 w2 = sm->sw2[half][o][2], w3 = sm->sw2[half][o][3];
        __half2 hl = __hmul2(w0, u2h(q0.x));
        hl = __hfma2(w1, u2h(q1.x), hl);
        hl = __hfma2(w2, u2h(q2.x), hl);
        hl = __hfma2(w3, u2h(q3.x), hl);
        __half2 hh = __hmul2(w0, u2h(q0.y));
        hh = __hfma2(w1, u2h(q1.y), hh);
        hh = __hfma2(w2, u2h(q2.y), hh);
        hh = __hfma2(w3, u2h(q3.y), hh);
        hl = __hmax2(hl, z2);
        hh = __hmax2(hh, z2);
        // pair-max with neighbor osub (16 lanes away), packed
        hl = __hmax2(hl, u2h(__shfl_xor_sync(0xffffffffu, h2u(hl), 16)));
        hh = __hmax2(hh, u2h(__shfl_xor_sync(0xffffffffu, h2u(hh), 16)));
        float2 f0 = __half22float2(hl);
        float2 f1 = __half22float2(hh);
        acc.x += f0.x; acc.y += f0.y; acc.z += f1.x; acc.w += f1.y;
    }
    if ((osub & 1) == 0) {
        int w = (htid >> 5) & 3;
        *(float4*)&sm->sacc[half][w][c4 * 4] = acc;
    }
    __syncthreads();

    if (htid < 64) {
        int u = htid;
        float fv = sm->sacc[half][0][u] + sm->sacc[half][1][u] +
                   sm->sacc[half][2][u] + sm->sacc[half][3][u];
        d_g[stage][(size_t)row * 64 + u] = fv * (1.0f / 36.0f);
    }
}

// ===========================================================================
// Head blocks: 16 rows, 256 threads. which: 0=cls,1=reg,2=loc
// ===========================================================================
struct SmemH16 {
    float A[16][65];
    float B[16][65];
    float W[64*64];
};

__device__ __forceinline__ void gemm16(
    SmemH16* sm, const float (*In)[65], float (*Out)[65],
    const float* __restrict__ Wg, const float* __restrict__ bg, int tid)
{
    __syncthreads();
    for (int i = tid; i < 4096; i += 256) sm->W[i] = Wg[i];
    __syncthreads();
    int u0 = (tid & 15) * 4, r = tid >> 4;
    float4 acc = make_float4(bg[u0], bg[u0 + 1], bg[u0 + 2], bg[u0 + 3]);
#pragma unroll 8
    for (int k = 0; k < 64; k++) {
        float4 w4 = *(const float4*)&sm->W[k * 64 + u0];
        float a = In[r][k];
        acc.x = fmaf(a, w4.x, acc.x);
        acc.y = fmaf(a, w4.y, acc.y);
        acc.z = fmaf(a, w4.z, acc.z);
        acc.w = fmaf(a, w4.w, acc.w);
    }
    __syncthreads();
    Out[r][u0]     = fmaxf(acc.x, 0.f);
    Out[r][u0 + 1] = fmaxf(acc.y, 0.f);
    Out[r][u0 + 2] = fmaxf(acc.z, 0.f);
    Out[r][u0 + 3] = fmaxf(acc.w, 0.f);
}

__device__ __forceinline__ void head_body(
    SmemH16* sm, int s, int row0, int which,
    const float* __restrict__ fc_w, const float* __restrict__ fc_b,
    const float* __restrict__ hw,  const float* __restrict__ hb,
    const float* __restrict__ how, const float* __restrict__ hob,
    float* __restrict__ out)
{
    int tid = threadIdx.x;
    float inv = 1.0f / (float)(s + 1);
    for (int e = tid; e < 1024; e += 256) {
        int r = e >> 6, u = e & 63;
        size_t off = (size_t)(row0 + r) * 64 + u;
        float fv = d_g[0][off];
        if (s >= 1) fv += d_g[1][off];
        if (s >= 2) fv += d_g[2][off];
        sm->A[r][u] = fv * inv;
    }
    gemm16(sm, sm->A, sm->B, fc_w, fc_b, tid);
    gemm16(sm, sm->B, sm->A, hw, hb, tid);
    gemm16(sm, sm->A, sm->B, hw + 4096, hb + 64, tid);
    __syncthreads();

    if (which == 0) {
        if (tid < 32) {
            int r = tid >> 1, u = tid & 1;
            float a = hob[u];
#pragma unroll
            for (int i = 0; i < 64; i++) a = fmaf(sm->B[r][i], how[i * 2 + u], a);
            out[((size_t)s * ROWS + row0 + r) * 79 + u] = a;
        }
    } else if (which == 1) {
        for (int e = tid; e < 16 * 76; e += 256) {
            int r = e / 76, u = e - r * 76;
            float a = hob[u];
#pragma unroll
            for (int i = 0; i < 64; i++) a = fmaf(sm->B[r][i], how[i * 76 + u], a);
            int row = row0 + r;
            out[((size_t)s * ROWS + row) * 79 + 2 + u] = a;
            if (u >= 4) d_prior[(size_t)row * 72 + (u - 4)] = sigm(a);
        }
    } else {
        if (tid < 16) {
            float a = hob[0];
#pragma unroll
            for (int i = 0; i < 64; i++) a = fmaf(sm->B[tid][i], how[i], a);
            out[((size_t)s * ROWS + row0 + tid) * 79 + 78] = a;
        }
    }
}

// ===========================================================================
// Kernels
// ===========================================================================
__global__ __launch_bounds__(256)
void kT0(const float* __restrict__ x2, const float* __restrict__ lsgi_w) {
    __shared__ SmemT sm;
    kT_body(&sm, x2, lsgi_w, d_Ft0, blockIdx.x * 64, 250);
}

union USmA { SmemT t; SmemS s; };
union USmB { SmemS s; SmemH16 h; };

__global__ __launch_bounds__(256)
void kMixA(const float* __restrict__ x0, const float* __restrict__ x1,
           const float* __restrict__ lsgi_w,
           const float* __restrict__ prior0, const float* __restrict__ l_weight)
{
    __shared__ USmA sm;
    int bx = blockIdx.x;
    bool isT; int idx;
    if (bx < 5000) { isT = ((bx & 1) == 0); idx = bx >> 1; }
    else           { isT = false; idx = 2500 + (bx - 5000); }

    if (isT) {
        if (idx < 500) kT_body(&sm.t, x1, lsgi_w + 4096, d_Ft1, idx * 64, 1000);
        else           kT_body(&sm.t, x0, lsgi_w + 8192, d_Ft2, (idx - 500) * 64, 4000);
    } else {
        kS_body(&sm.s, 0, idx * 2, 10, 25, prior0, l_weight);
    }
}

__global__ __launch_bounds__(256)
void kReg(int s,
          const float* __restrict__ fc_w,  const float* __restrict__ fc_b,
          const float* __restrict__ reg_w, const float* __restrict__ reg_b,
          const float* __restrict__ reg_ow,const float* __restrict__ reg_ob,
          float* __restrict__ out)
{
    __shared__ SmemH16 sm;
    head_body(&sm, s, blockIdx.x * 16, 1, fc_w, fc_b, reg_w, reg_b, reg_ow, reg_ob, out);
}

// heads (stage sS-1) scheduled FIRST, then kS(stage sS)
__global__ __launch_bounds__(256)
void kMixB(int sS, int H, int W,
           const float* __restrict__ prior0, const float* __restrict__ l_weight,
           const float* __restrict__ fc_w,  const float* __restrict__ fc_b,
           const float* __restrict__ cls_w, const float* __restrict__ cls_b,
           const float* __restrict__ cls_ow,const float* __restrict__ cls_ob,
           const float* __restrict__ loc_w, const float* __restrict__ loc_b,
           const float* __restrict__ loc_ow,const float* __restrict__ loc_ob,
           float* __restrict__ out)
{
    __shared__ USmB sm;
    int bx = blockIdx.x;
    if (bx < 384) {
        head_body(&sm.h, sS - 1, bx * 16, 0,
                  fc_w, fc_b, cls_w, cls_b, cls_ow, cls_ob, out);
    } else if (bx < 768) {
        head_body(&sm.h, sS - 1, (bx - 384) * 16, 2,
                  fc_w, fc_b, loc_w, loc_b, loc_ow, loc_ob, out);
    } else {
        kS_body(&sm.s, sS, (bx - 768) * 2, H, W, prior0, l_weight);
    }
}

__global__ __launch_bounds__(256)
void kFinal(const float* __restrict__ fc_w,  const float* __restrict__ fc_b,
            const float* __restrict__ cls_w, const float* __restrict__ cls_b,
            const float* __restrict__ cls_ow,const float* __restrict__ cls_ob,
            const float* __restrict__ reg_w, const float* __restrict__ reg_b,
            const float* __restrict__ reg_ow,const float* __restrict__ reg_ob,
            const float* __restrict__ loc_w, const float* __restrict__ loc_b,
            const float* __restrict__ loc_ow,const float* __restrict__ loc_ob,
            float* __restrict__ out)
{
    __shared__ SmemH16 sm;
    int t = blockIdx.x / 384;
    int row0 = (blockIdx.x - t * 384) * 16;
    if (t == 0)
        head_body(&sm, 2, row0, 1, fc_w, fc_b, reg_w, reg_b, reg_ow, reg_ob, out);
    else if (t == 1)
        head_body(&sm, 2, row0, 0, fc_w, fc_b, cls_w, cls_b, cls_ow, cls_ob, out);
    else
        head_body(&sm, 2, row0, 2, fc_w, fc_b, loc_w, loc_b, loc_ow, loc_ob, out);
}

// ===========================================================================
extern "C" void kernel_launch(void* const* d_in, const int* in_sizes, int n_in,
                              void* d_out, int out_size) {
    const float* x0       = (const float*)d_in[0];
    const float* x1       = (const float*)d_in[1];
    const float* x2       = (const float*)d_in[2];
    const float* prior0   = (const float*)d_in[3];
    const float* l_weight = (const float*)d_in[4];
    const float* lsgi_w   = (const float*)d_in[5];
    const float* fc_w     = (const float*)d_in[6];
    const float* fc_b     = (const float*)d_in[7];
    const float* cls_w    = (const float*)d_in[8];
    const float* cls_b    = (const float*)d_in[9];
    const float* cls_ow   = (const float*)d_in[10];
    const float* cls_ob   = (const float*)d_in[11];
    const float* reg_w    = (const float*)d_in[12];
    const float* reg_b    = (const float*)d_in[13];
    const float* reg_ow   = (const float*)d_in[14];
    const float* reg_ob   = (const float*)d_in[15];
    const float* loc_w    = (const float*)d_in[16];
    const float* loc_b    = (const float*)d_in[17];
    const float* loc_ow   = (const float*)d_in[18];
    const float* loc_ob   = (const float*)d_in[19];
    float* out = (float*)d_out;

    kT0<<<125, 256>>>(x2, lsgi_w);
    kMixA<<<5572, 256>>>(x0, x1, lsgi_w, prior0, l_weight);

    kReg<<<384, 256>>>(0, fc_w, fc_b, reg_w, reg_b, reg_ow, reg_ob, out);

    kMixB<<<3840, 256>>>(1, 20, 50, prior0, l_weight, fc_w, fc_b,
                         cls_w, cls_b, cls_ow, cls_ob,
                         loc_w, loc_b, loc_ow, loc_ob, out);

    kReg<<<384, 256>>>(1, fc_w, fc_b, reg_w, reg_b, reg_ow, reg_ob, out);

    kMixB<<<3840, 256>>>(2, 40, 100, prior0, l_weight, fc_w, fc_b,
                         cls_w, cls_b, cls_ow, cls_ob,
                         loc_w, loc_b, loc_ow, loc_ob, out);

    kFinal<<<1152, 256>>>(fc_w, fc_b, cls_w, cls_b, cls_ow, cls_ob,
                          reg_w, reg_b, reg_ow, reg_ob,
                          loc_w, loc_b, loc_ow, loc_ob, out);
}

// round 11
// speedup vs baseline: 1.5661x; 1.5661x over previous
#include <cuda_runtime.h>
#include <math.h>

#define ROWS 6144            // B*Np = 32*192

__device__ float d_Ft0[32*250*64];     // stage0: x2 (10x25)
__device__ float d_Ft1[32*1000*64];    // stage1: x1 (20x50)
__device__ float d_Ft2[32*4000*64];    // stage2: x0 (40x100)
__device__ float d_prior[ROWS*72];
__device__ float d_g[3][ROWS*64];

__device__ __forceinline__ float sigm(float x) { return 1.0f / (1.0f + expf(-x)); }

// ===========================================================================
// kT body: transpose+matmul. 64 pixels x 64 out-channels per block, 256 thr.
// ===========================================================================
struct SmemT {
    float sin_[64][65];
    float sW[64*64];
};

__device__ __forceinline__ void kT_body(
    SmemT* sm, const float* __restrict__ feat, const float* __restrict__ Wg,
    float* __restrict__ outp, int p0, int HW)
{
    int tid = threadIdx.x;
    for (int i = tid; i < 4096; i += 256) sm->sW[i] = Wg[i];
    for (int e = tid; e < 4096; e += 256) {
        int c = e >> 6, p = e & 63;
        int gp = p0 + p;
        int b = gp / HW, hw = gp - b * HW;
        sm->sin_[p][c] = feat[(size_t)(b * 64 + c) * HW + hw];
    }
    __syncthreads();

    int cgrp = tid & 15, pgrp = tid >> 4;
    float acc[4][4];
#pragma unroll
    for (int i = 0; i < 4; i++)
#pragma unroll
        for (int j = 0; j < 4; j++) acc[i][j] = 0.f;

#pragma unroll 8
    for (int c = 0; c < 64; c++) {
        float4 w4 = *(const float4*)&sm->sW[c * 64 + cgrp * 4];
#pragma unroll
        for (int pp = 0; pp < 4; pp++) {
            float sv = sm->sin_[pgrp * 4 + pp][c];
            acc[pp][0] = fmaf(sv, w4.x, acc[pp][0]);
            acc[pp][1] = fmaf(sv, w4.y, acc[pp][1]);
            acc[pp][2] = fmaf(sv, w4.z, acc[pp][2]);
            acc[pp][3] = fmaf(sv, w4.w, acc[pp][3]);
        }
    }
#pragma unroll
    for (int pp = 0; pp < 4; pp++) {
        float4 r = make_float4(acc[pp][0], acc[pp][1], acc[pp][2], acc[pp][3]);
        *(float4*)&outp[(size_t)(p0 + pgrp * 4 + pp) * 64 + cgrp * 4] = r;
    }
}

// ===========================================================================
// kS body: sample + gate + relu + pair-max + group mean -> d_g[stage]
// 2 rows per 256-thread block.
// ===========================================================================
struct SmemS {
    int   sidx[2][72][4];
    float swt[2][72][4];
    float sgate[72];
    float sacc[2][4][64];
};

__device__ __forceinline__ void kS_body(
    SmemS* sm, int stage, int row0, int H, int W,
    const float* __restrict__ prior0, const float* __restrict__ l_weight)
{
    int tid = threadIdx.x;
    int htid = tid & 127, half = tid >> 7;
    int row = row0 + half;
    int b = row / 192, n = row - b * 192;

    if (tid < 72) sm->sgate[tid] = sigm(l_weight[tid]);
    if (htid < 72) {
        int o = htid;
        float px = (stage == 0) ? prior0[n * 72 + o] : d_prior[row * 72 + o];
        float gx = px * 2.0f - 1.0f;
        float ix = (gx + 1.0f) * 0.5f * (float)(W - 1);
        float yo = 1.0f - (float)o * (1.0f / 71.0f);
        float gy = yo * 2.0f - 1.0f;
        float iy = (gy + 1.0f) * 0.5f * (float)(H - 1);
        float ix0f = floorf(ix), iy0f = floorf(iy);
        float wx = ix - ix0f, wy = iy - iy0f;
        int ix0 = min(max((int)ix0f, 0), W - 1);
        int iy0 = min(max((int)iy0f, 0), H - 1);
        int ix1 = min(ix0 + 1, W - 1);
        int iy1 = min(iy0 + 1, H - 1);
        sm->sidx[half][o][0] = (iy0 * W + ix0) * 64;
        sm->sidx[half][o][1] = (iy0 * W + ix1) * 64;
        sm->sidx[half][o][2] = (iy1 * W + ix0) * 64;
        sm->sidx[half][o][3] = (iy1 * W + ix1) * 64;
        sm->swt[half][o][0] = (1.f - wx) * (1.f - wy);
        sm->swt[half][o][1] = wx * (1.f - wy);
        sm->swt[half][o][2] = (1.f - wx) * wy;
        sm->swt[half][o][3] = wx * wy;
    }
    __syncthreads();

    const float* Ft = (stage == 0) ? d_Ft0 : (stage == 1 ? d_Ft1 : d_Ft2);
    const float* base = Ft + (size_t)b * ((size_t)H * W * 64);
    int c4 = htid & 15, osub = htid >> 4;

    float4 acc = make_float4(0.f, 0.f, 0.f, 0.f);
#pragma unroll
    for (int it = 0; it < 9; it++) {
        int o = it * 8 + osub;
        const int* si = sm->sidx[half][o];
        float4 a0 = *((const float4*)(base + si[0]) + c4);
        float4 a1 = *((const float4*)(base + si[1]) + c4);
        float4 a2 = *((const float4*)(base + si[2]) + c4);
        float4 a3 = *((const float4*)(base + si[3]) + c4);
        float w0 = sm->swt[half][o][0], w1 = sm->swt[half][o][1];
        float w2 = sm->swt[half][o][2], w3 = sm->swt[half][o][3];
        float g = sm->sgate[o];
        float4 r;
        r.x = fmaxf(0.f, g * (w0 * a0.x + w1 * a1.x + w2 * a2.x + w3 * a3.x));
        r.y = fmaxf(0.f, g * (w0 * a0.y + w1 * a1.y + w2 * a2.y + w3 * a3.y));
        r.z = fmaxf(0.f, g * (w0 * a0.z + w1 * a1.z + w2 * a2.z + w3 * a3.z));
        r.w = fmaxf(0.f, g * (w0 * a0.w + w1 * a1.w + w2 * a2.w + w3 * a3.w));
        float qx = __shfl_xor_sync(0xffffffffu, r.x, 16);
        float qy = __shfl_xor_sync(0xffffffffu, r.y, 16);
        float qz = __shfl_xor_sync(0xffffffffu, r.z, 16);
        float qw = __shfl_xor_sync(0xffffffffu, r.w, 16);
        if ((osub & 1) == 0) {
            acc.x += fmaxf(r.x, qx);
            acc.y += fmaxf(r.y, qy);
            acc.z += fmaxf(r.z, qz);
            acc.w += fmaxf(r.w, qw);
        }
    }
    if ((osub & 1) == 0) {
        int w = (htid >> 5) & 3;
        *(float4*)&sm->sacc[half][w][c4 * 4] = acc;
    }
    __syncthreads();

    if (htid < 64) {
        int u = htid;
        float fv = sm->sacc[half][0][u] + sm->sacc[half][1][u] +
                   sm->sacc[half][2][u] + sm->sacc[half][3][u];
        d_g[stage][(size_t)row * 64 + u] = fv * (1.0f / 36.0f);
    }
}

// ===========================================================================
// kH3: 3-way-split heads. 32 rows/block, 256 threads, grid = 576.
// which = bx/192: 0=reg, 1=cls, 2=loc. Each recomputes the shared fc layer.
// Serial gemm depth per block: 4 (was 10).
// ===========================================================================
struct SmemH32 {
    float A[32][65];
    float B[32][65];
    float W[64*64];
};

__device__ __forceinline__ void gemm32(
    SmemH32* sm, const float (*In)[65], float (*Out)[65],
    const float* __restrict__ Wg, const float* __restrict__ bg, int tid)
{
    __syncthreads();                          // previous readers of W done
    for (int i = tid; i < 4096; i += 256) sm->W[i] = Wg[i];
    __syncthreads();
    int u0 = (tid & 15) * 4, r0 = (tid >> 4) * 2;
    float b0 = bg[u0], b1 = bg[u0 + 1], b2 = bg[u0 + 2], b3 = bg[u0 + 3];
    float acc[2][4] = {{b0, b1, b2, b3}, {b0, b1, b2, b3}};
#pragma unroll 8
    for (int k = 0; k < 64; k++) {
        float4 w4 = *(const float4*)&sm->W[k * 64 + u0];
        float a0 = In[r0][k], a1 = In[r0 + 1][k];
        acc[0][0] = fmaf(a0, w4.x, acc[0][0]);
        acc[0][1] = fmaf(a0, w4.y, acc[0][1]);
        acc[0][2] = fmaf(a0, w4.z, acc[0][2]);
        acc[0][3] = fmaf(a0, w4.w, acc[0][3]);
        acc[1][0] = fmaf(a1, w4.x, acc[1][0]);
        acc[1][1] = fmaf(a1, w4.y, acc[1][1]);
        acc[1][2] = fmaf(a1, w4.z, acc[1][2]);
        acc[1][3] = fmaf(a1, w4.w, acc[1][3]);
    }
    __syncthreads();                          // reads of In done -> Out may alias
#pragma unroll
    for (int r = 0; r < 2; r++)
#pragma unroll
        for (int j = 0; j < 4; j++)
            Out[r0 + r][u0 + j] = fmaxf(acc[r][j], 0.f);
}

__global__ __launch_bounds__(256, 4)
void kH3(int s,
         const float* __restrict__ fc_w,  const float* __restrict__ fc_b,
         const float* __restrict__ cls_w, const float* __restrict__ cls_b,
         const float* __restrict__ cls_ow,const float* __restrict__ cls_ob,
         const float* __restrict__ reg_w, const float* __restrict__ reg_b,
         const float* __restrict__ reg_ow,const float* __restrict__ reg_ob,
         const float* __restrict__ loc_w, const float* __restrict__ loc_b,
         const float* __restrict__ loc_ow,const float* __restrict__ loc_ob,
         float* __restrict__ out)
{
    __shared__ SmemH32 sm;
    int tid = threadIdx.x;
    int which = blockIdx.x / 192;            // 0=reg, 1=cls, 2=loc
    int row0 = (blockIdx.x - which * 192) * 32;
    float inv = 1.0f / (float)(s + 1);

    for (int e = tid; e < 2048; e += 256) {
        int r = e >> 6, u = e & 63;
        size_t off = (size_t)(row0 + r) * 64 + u;
        float fv = d_g[0][off];
        if (s >= 1) fv += d_g[1][off];
        if (s >= 2) fv += d_g[2][off];
        sm.A[r][u] = fv * inv;
    }
    gemm32(&sm, sm.A, sm.B, fc_w, fc_b, tid);          // B = relu(fc)

    const float* hw  = (which == 0) ? reg_w : (which == 1 ? cls_w : loc_w);
    const float* hb  = (which == 0) ? reg_b : (which == 1 ? cls_b : loc_b);
    gemm32(&sm, sm.B, sm.A, hw, hb, tid);              // layer 1: B -> A
    gemm32(&sm, sm.A, sm.B, hw + 4096, hb + 64, tid);  // layer 2: A -> B
    __syncthreads();

    if (which == 0) {            // reg: 76 outputs/row + prior feedback
        for (int e = tid; e < 32 * 76; e += 256) {
            int r = e / 76, u = e - r * 76;
            float a = reg_ob[u];
#pragma unroll
            for (int i = 0; i < 64; i++) a = fmaf(sm.B[r][i], reg_ow[i * 76 + u], a);
            int row = row0 + r;
            out[((size_t)s * ROWS + row) * 79 + 2 + u] = a;
            if (u >= 4) d_prior[(size_t)row * 72 + (u - 4)] = sigm(a);
        }
    } else if (which == 1) {     // cls: 2 outputs/row
        if (tid < 64) {
            int r = tid >> 1, u = tid & 1;
            float a = cls_ob[u];
#pragma unroll
            for (int i = 0; i < 64; i++) a = fmaf(sm.B[r][i], cls_ow[i * 2 + u], a);
            out[((size_t)s * ROWS + row0 + r) * 79 + u] = a;
        }
    } else {                     // loc: 1 output/row
        if (tid < 32) {
            float a = loc_ob[0];
#pragma unroll
            for (int i = 0; i < 64; i++) a = fmaf(sm.B[tid][i], loc_ow[i], a);
            out[((size_t)s * ROWS + row0 + tid) * 79 + 78] = a;
        }
    }
}

// ===========================================================================
// Kernels
// ===========================================================================
__global__ __launch_bounds__(256)
void kT0(const float* __restrict__ x2, const float* __restrict__ lsgi_w) {
    __shared__ SmemT sm;
    kT_body(&sm, x2, lsgi_w, d_Ft0, blockIdx.x * 64, 250);
}

// Mixed launch: interleaved kS(stage0) blocks (3072) + kT(stage1/2) blocks (2500)
__global__ __launch_bounds__(256)
void kMix(const float* __restrict__ x0, const float* __restrict__ x1,
          const float* __restrict__ lsgi_w,
          const float* __restrict__ prior0, const float* __restrict__ l_weight)
{
    __shared__ union USm { SmemT t; SmemS s; } sm;
    int bx = blockIdx.x;
    bool isT; int idx;
    if (bx < 5000) { isT = ((bx & 1) == 0); idx = bx >> 1; }
    else           { isT = false; idx = 2500 + (bx - 5000); }

    if (isT) {
        if (idx < 500) kT_body(&sm.t, x1, lsgi_w + 4096, d_Ft1, idx * 64, 1000);
        else           kT_body(&sm.t, x0, lsgi_w + 8192, d_Ft2, (idx - 500) * 64, 4000);
    } else {
        kS_body(&sm.s, 0, idx * 2, 10, 25, prior0, l_weight);
    }
}

__global__ __launch_bounds__(256, 8)   // cap regs at 32 -> 64 warps/SM
void kSk(int stage, int H, int W,
         const float* __restrict__ prior0, const float* __restrict__ l_weight)
{
    __shared__ SmemS sm;
    kS_body(&sm, stage, blockIdx.x * 2, H, W, prior0, l_weight);
}

// ===========================================================================
extern "C" void kernel_launch(void* const* d_in, const int* in_sizes, int n_in,
                              void* d_out, int out_size) {
    const float* x0       = (const float*)d_in[0];
    const float* x1       = (const float*)d_in[1];
    const float* x2       = (const float*)d_in[2];
    const float* prior0   = (const float*)d_in[3];
    const float* l_weight = (const float*)d_in[4];
    const float* lsgi_w   = (const float*)d_in[5];
    const float* fc_w     = (const float*)d_in[6];
    const float* fc_b     = (const float*)d_in[7];
    const float* cls_w    = (const float*)d_in[8];
    const float* cls_b    = (const float*)d_in[9];
    const float* cls_ow   = (const float*)d_in[10];
    const float* cls_ob   = (const float*)d_in[11];
    const float* reg_w    = (const float*)d_in[12];
    const float* reg_b    = (const float*)d_in[13];
    const float* reg_ow   = (const float*)d_in[14];
    const float* reg_ob   = (const float*)d_in[15];
    const float* loc_w    = (const float*)d_in[16];
    const float* loc_b    = (const float*)d_in[17];
    const float* loc_ow   = (const float*)d_in[18];
    const float* loc_ob   = (const float*)d_in[19];
    float* out = (float*)d_out;

    kT0<<<125, 256>>>(x2, lsgi_w);
    kMix<<<5572, 256>>>(x0, x1, lsgi_w, prior0, l_weight);
    kH3<<<576, 256>>>(0, fc_w, fc_b, cls_w, cls_b, cls_ow, cls_ob,
                      reg_w, reg_b, reg_ow, reg_ob, loc_w, loc_b, loc_ow, loc_ob, out);

    kSk<<<3072, 256>>>(1, 20, 50, prior0, l_weight);
    kH3<<<576, 256>>>(1, fc_w, fc_b, cls_w, cls_b, cls_ow, cls_ob,
                      reg_w, reg_b, reg_ow, reg_ob, loc_w, loc_b, loc_ow, loc_ob, out);

    kSk<<<3072, 256>>>(2, 40, 100, prior0, l_weight);
    kH3<<<576, 256>>>(2, fc_w, fc_b, cls_w, cls_b, cls_ow, cls_ob,
                      reg_w, reg_b, reg_ow, reg_ob, loc_w, loc_b, loc_ow, loc_ob, out);
}